// round 5
// baseline (speedup 1.0000x reference)
#include <cuda_runtime.h>
#include <cstdint>

#define S_LEN  4096
#define BATCH  2
#define DMODEL 768
#define NHEAD  12
#define HDIM   64
#define WSZ    256
#define NROWS  (S_LEN * BATCH)   // 8192

// scratch (device globals: allowed, no allocation)
__device__ float g_q [(size_t)NROWS * DMODEL];
__device__ float g_k [(size_t)NROWS * DMODEL];
__device__ float g_v [(size_t)NROWS * DMODEL];
__device__ float g_ar[(size_t)NROWS * DMODEL];        // tf32-rounded activations
__device__ float g_w3[(size_t)3 * DMODEL * DMODEL];   // tf32-rounded W (row-major)

// ---------------------------------------------------------------------------
// helpers
// ---------------------------------------------------------------------------
__device__ __forceinline__ unsigned long long pk2(float x, float y) {
    unsigned long long r;
    asm("mov.b64 %0,{%1,%2};" : "=l"(r) : "f"(x), "f"(y));
    return r;
}
__device__ __forceinline__ void upk2(unsigned long long v, float& x, float& y) {
    asm("mov.b64 {%0,%1},%2;" : "=f"(x), "=f"(y) : "l"(v));
}
__device__ __forceinline__ unsigned long long fma2_(unsigned long long a,
                                                    unsigned long long b,
                                                    unsigned long long c) {
    unsigned long long d;
    asm("fma.rn.f32x2 %0,%1,%2,%3;" : "=l"(d) : "l"(a), "l"(b), "l"(c));
    return d;
}
__device__ __forceinline__ unsigned long long mul2_(unsigned long long a,
                                                    unsigned long long b) {
    unsigned long long d;
    asm("mul.rn.f32x2 %0,%1,%2;" : "=l"(d) : "l"(a), "l"(b));
    return d;
}
__device__ __forceinline__ float tf32f(float x) {
    uint32_t u;
    asm("cvt.rna.tf32.f32 %0,%1;" : "=r"(u) : "f"(x));
    return __uint_as_float(u);
}
__device__ __forceinline__ uint32_t s2u(const void* p) {
    uint32_t a;
    asm("{ .reg .u64 t; cvta.to.shared.u64 t, %1; cvt.u32.u64 %0, t; }"
        : "=r"(a) : "l"(p));
    return a;
}
__device__ __forceinline__ void cpa16(uint32_t dst, const void* src) {
    asm volatile("cp.async.cg.shared.global [%0], [%1], 16;"
                 :: "r"(dst), "l"(src));
}
__device__ __forceinline__ void mma_tf32(float c[4], const uint32_t a[4],
                                         const uint32_t b[2]) {
    asm volatile(
        "mma.sync.aligned.m16n8k8.row.col.f32.tf32.tf32.f32 "
        "{%0,%1,%2,%3},{%4,%5,%6,%7},{%8,%9},{%0,%1,%2,%3};"
        : "+f"(c[0]), "+f"(c[1]), "+f"(c[2]), "+f"(c[3])
        : "r"(a[0]), "r"(a[1]), "r"(a[2]), "r"(a[3]), "r"(b[0]), "r"(b[1]));
}

// ---------------------------------------------------------------------------
// prepasses: tf32 rounding (RNA) of activations and weights
// ---------------------------------------------------------------------------
__global__ __launch_bounds__(256) void round_val(const float* __restrict__ val)
{
    size_t i = ((size_t)blockIdx.x * 256 + threadIdx.x) * 4;
    float4 v = *(const float4*)(val + i);
    v.x = tf32f(v.x); v.y = tf32f(v.y); v.z = tf32f(v.z); v.w = tf32f(v.w);
    *(float4*)(g_ar + i) = v;
}

__global__ __launch_bounds__(256) void round_w(
    const float* __restrict__ Wq, const float* __restrict__ Wk,
    const float* __restrict__ Wv)
{
    const int z = blockIdx.y;
    const float* W = (z == 0) ? Wq : (z == 1) ? Wk : Wv;
    size_t i = ((size_t)blockIdx.x * 256 + threadIdx.x) * 4;
    float4 v = *(const float4*)(W + i);
    v.x = tf32f(v.x); v.y = tf32f(v.y); v.z = tf32f(v.z); v.w = tf32f(v.w);
    *(float4*)(g_w3 + (size_t)z * DMODEL * DMODEL + i) = v;
}

// ---------------------------------------------------------------------------
// Kernel 1: QKV projection, legacy mma.sync tf32, cp.async 3-stage pipeline.
// CTA tile 256x128, 8 warps (4m x 2n), warp tile 64x64, KC=32.
//   A smem: [256][36] (row-major, padded)     16B-chunk & frag conflict-free
//   B smem: [32][136] (k-major, padded)       16B-chunk & frag conflict-free
// ---------------------------------------------------------------------------
#define GM 256
#define GN 128
#define KC 32
#define NST (DMODEL / KC)             // 24
#define ASTR 36
#define BSTR 136
#define AWORDS (GM * ASTR)            // 9216
#define STWORDS (AWORDS + KC * BSTR)  // 13568
#define SMEM_G (3 * STWORDS * 4)      // 162816 bytes

__global__ __launch_bounds__(256, 1) void qkv_gemm(
    const float* __restrict__ bq, const float* __restrict__ bk,
    const float* __restrict__ bv)
{
    extern __shared__ __align__(16) float smem[];
    const uint32_t sb = s2u(smem);

    const int tid  = threadIdx.x;
    const int lane = tid & 31;
    const int w    = tid >> 5;
    const int wm   = (w & 3) * 64;
    const int wn   = (w >> 2) * 64;
    const int qd   = lane >> 2;      // 0..7
    const int kl   = lane & 3;       // 0..3

    const int z = blockIdx.z;
    const float* __restrict__ Wt   = g_w3 + (size_t)z * DMODEL * DMODEL;
    const float* __restrict__ bias = (z == 0) ? bq : (z == 1) ? bk : bv;
    float* outp = (z == 0) ? g_q : (z == 1) ? g_k : g_v;
    const float scale = (z == 0) ? 0.125f : 1.0f;
    const int bm = blockIdx.y * GM;
    const int bn = blockIdx.x * GN;

    float acc[4][8][4];
#pragma unroll
    for (int mt = 0; mt < 4; mt++)
#pragma unroll
        for (int nt = 0; nt < 8; nt++)
#pragma unroll
            for (int i = 0; i < 4; i++) acc[mt][nt][i] = 0.f;

    auto load_stage = [&](int s) {
        const uint32_t base = sb + (uint32_t)(s % 3) * (STWORDS * 4);
        const int k0 = s * KC;
        // A: 256 rows x 8 chunks = 2048 chunks
#pragma unroll
        for (int i = 0; i < 8; i++) {
            const int c  = tid + 256 * i;
            const int m  = c >> 3;
            const int k4 = (c & 7) * 4;
            cpa16(base + (uint32_t)(m * ASTR + k4) * 4,
                  g_ar + (size_t)(bm + m) * DMODEL + k0 + k4);
        }
        // B: 32 rows x 32 chunks = 1024 chunks
#pragma unroll
        for (int i = 0; i < 4; i++) {
            const int c  = tid + 256 * i;
            const int kr = c >> 5;
            const int n4 = (c & 31) * 4;
            cpa16(base + (uint32_t)(AWORDS + kr * BSTR + n4) * 4,
                  Wt + (size_t)(k0 + kr) * DMODEL + bn + n4);
        }
        asm volatile("cp.async.commit_group;" ::: "memory");
    };

    load_stage(0); load_stage(1); load_stage(2);

    for (int s = 0; s < NST; s++) {
        asm volatile("cp.async.wait_group 2;" ::: "memory");
        __syncthreads();

        const float* As = smem + (s % 3) * STWORDS;
        const float* Bs = As + AWORDS;

#pragma unroll
        for (int ks = 0; ks < 4; ks++) {
            const int kc = ks * 8 + kl;
            uint32_t af[4][4];
#pragma unroll
            for (int mt = 0; mt < 4; mt++) {
                const int r = wm + mt * 16 + qd;
                af[mt][0] = __float_as_uint(As[r * ASTR + kc]);
                af[mt][1] = __float_as_uint(As[(r + 8) * ASTR + kc]);
                af[mt][2] = __float_as_uint(As[r * ASTR + kc + 4]);
                af[mt][3] = __float_as_uint(As[(r + 8) * ASTR + kc + 4]);
            }
            uint32_t bf[8][2];
#pragma unroll
            for (int nt = 0; nt < 8; nt++) {
                const int cc = wn + nt * 8 + qd;
                bf[nt][0] = __float_as_uint(Bs[kc * BSTR + cc]);
                bf[nt][1] = __float_as_uint(Bs[(kc + 4) * BSTR + cc]);
            }
#pragma unroll
            for (int mt = 0; mt < 4; mt++)
#pragma unroll
                for (int nt = 0; nt < 8; nt++)
                    mma_tf32(acc[mt][nt], af[mt], bf[nt]);
        }

        __syncthreads();
        if (s + 3 < NST) load_stage(s + 3);
        else asm volatile("cp.async.commit_group;" ::: "memory");  // keep count
    }

    // epilogue: bias + scale, 8B stores (32B-sector aligned per quad)
#pragma unroll
    for (int mt = 0; mt < 4; mt++) {
        const int row0 = bm + wm + mt * 16 + qd;
#pragma unroll
        for (int nt = 0; nt < 8; nt++) {
            const int col = bn + wn + nt * 8 + 2 * kl;
            const float2 b2 = *(const float2*)(bias + col);
            float2 o0, o1;
            o0.x = (acc[mt][nt][0] + b2.x) * scale;
            o0.y = (acc[mt][nt][1] + b2.y) * scale;
            o1.x = (acc[mt][nt][2] + b2.x) * scale;
            o1.y = (acc[mt][nt][3] + b2.y) * scale;
            *(float2*)(outp + (size_t)row0 * DMODEL + col)       = o0;
            *(float2*)(outp + (size_t)(row0 + 8) * DMODEL + col) = o1;
        }
    }
}

// ---------------------------------------------------------------------------
// Kernel 2: causal sliding-window attention.
// 4 lanes per query (lane&3 = 16-dim quarter), 4 queries per thread.
// Packed f32x2 FMA; rotated quarter-slot smem layout (conflict-free).
// ---------------------------------------------------------------------------
#define QBLK2 128
#define KT2   64

__global__ __launch_bounds__(128) void attn_kernel(float* __restrict__ out)
{
    __shared__ float Ks[KT2 * HDIM];
    __shared__ float Vs[KT2 * HDIM];

    const int tid  = threadIdx.x;
    const int lane = tid & 31;
    const int wid  = tid >> 5;
    const int h    = blockIdx.y;
    const int b    = blockIdx.z;
    const int q0   = blockIdx.x * QBLK2;
    const int wq0  = q0 + wid * 32;
    const int r    = lane >> 2;
    const int c    = lane & 3;

    int qi[4];
#pragma unroll
    for (int qq = 0; qq < 4; qq++) qi[qq] = wq0 + r + 8 * qq;

    unsigned long long q2[4][8];
#pragma unroll
    for (int qq = 0; qq < 4; qq++) {
        const ulonglong2* qg = (const ulonglong2*)(
            g_q + ((size_t)qi[qq] * BATCH + b) * DMODEL + h * HDIM + c * 16);
#pragma unroll
        for (int i = 0; i < 4; i++) {
            ulonglong2 t = qg[i];
            q2[qq][2 * i] = t.x; q2[qq][2 * i + 1] = t.y;
        }
    }

    unsigned long long acc2[4][8];
#pragma unroll
    for (int qq = 0; qq < 4; qq++)
#pragma unroll
        for (int i = 0; i < 8; i++) acc2[qq][i] = 0ull;
    float m[4] = {-1e30f, -1e30f, -1e30f, -1e30f};
    float l[4] = {0.f, 0.f, 0.f, 0.f};

    const int jstart = q0 - WSZ;

    for (int t = 0; t < 6; t++) {
        const int j0 = jstart + t * KT2;
        if (j0 + KT2 <= 0) continue;
        __syncthreads();
#pragma unroll
        for (int it = 0; it < 8; it++) {
            const int f   = tid + 128 * it;
            const int row = f >> 4;
            const int lc  = f & 15;
            const int cc  = lc >> 2;
            const int ii  = lc & 3;
            const int slot = cc * 4 + ((ii + cc) & 3);
            const int j = j0 + row;
            float4 kk4 = make_float4(0.f, 0.f, 0.f, 0.f);
            float4 vv4 = make_float4(0.f, 0.f, 0.f, 0.f);
            if (j >= 0 && j < S_LEN) {
                const size_t base =
                    ((size_t)j * BATCH + b) * DMODEL + h * HDIM + lc * 4;
                kk4 = *(const float4*)(g_k + base);
                vv4 = *(const float4*)(g_v + base);
            }
            *(float4*)&Ks[row * HDIM + slot * 4] = kk4;
            *(float4*)&Vs[row * HDIM + slot * 4] = vv4;
        }
        __syncthreads();

        for (int jj = 0; jj < KT2; jj++) {
            const int j = j0 + jj;
            if (j < 0 || j > wq0 + 31 || j < wq0 - WSZ) continue;

            unsigned long long k2[8];
#pragma unroll
            for (int i = 0; i < 4; i++) {
                const int slot = c * 4 + ((i + c) & 3);
                ulonglong2 kk = *(const ulonglong2*)&Ks[jj * HDIM + slot * 4];
                k2[2 * i] = kk.x; k2[2 * i + 1] = kk.y;
            }

            float p[4];
#pragma unroll
            for (int qq = 0; qq < 4; qq++) {
                unsigned long long s2 = 0ull;
#pragma unroll
                for (int i = 0; i < 8; i++) s2 = fma2_(q2[qq][i], k2[i], s2);
                float sx, sy;
                upk2(s2, sx, sy);
                float s = sx + sy;
                s += __shfl_xor_sync(0xffffffffu, s, 1);
                s += __shfl_xor_sync(0xffffffffu, s, 2);

                const bool valid = (j <= qi[qq]) && (j >= qi[qq] - WSZ);
                if (valid) {
                    if (s > m[qq]) {
                        const float sc = __expf(m[qq] - s);
                        m[qq] = s;
                        l[qq] *= sc;
                        const unsigned long long sc2 = pk2(sc, sc);
#pragma unroll
                        for (int i = 0; i < 8; i++)
                            acc2[qq][i] = mul2_(acc2[qq][i], sc2);
                    }
                    const float pp = __expf(s - m[qq]);
                    l[qq] += pp;
                    p[qq] = pp;
                } else {
                    p[qq] = 0.f;
                }
            }

            unsigned long long v2[8];
#pragma unroll
            for (int i = 0; i < 4; i++) {
                const int slot = c * 4 + ((i + c) & 3);
                ulonglong2 vv = *(const ulonglong2*)&Vs[jj * HDIM + slot * 4];
                v2[2 * i] = vv.x; v2[2 * i + 1] = vv.y;
            }
#pragma unroll
            for (int qq = 0; qq < 4; qq++) {
                const unsigned long long p2 = pk2(p[qq], p[qq]);
#pragma unroll
                for (int i = 0; i < 8; i++)
                    acc2[qq][i] = fma2_(p2, v2[i], acc2[qq][i]);
            }
        }
    }

#pragma unroll
    for (int qq = 0; qq < 4; qq++) {
        const float inv = 1.f / l[qq];
        float* og = out + ((size_t)qi[qq] * BATCH + b) * DMODEL + h * HDIM + c * 16;
#pragma unroll
        for (int i = 0; i < 4; i++) {
            float x0, y0, x1, y1;
            upk2(acc2[qq][2 * i], x0, y0);
            upk2(acc2[qq][2 * i + 1], x1, y1);
            *(float4*)(og + 4 * i) =
                make_float4(x0 * inv, y0 * inv, x1 * inv, y1 * inv);
        }
    }
}

// ---------------------------------------------------------------------------
extern "C" void kernel_launch(void* const* d_in, const int* in_sizes, int n_in,
                              void* d_out, int out_size)
{
    const float* val = (const float*)d_in[0];
    const float* Wq  = (const float*)d_in[1];
    const float* bq  = (const float*)d_in[2];
    const float* Wk  = (const float*)d_in[3];
    const float* bk  = (const float*)d_in[4];
    const float* Wv  = (const float*)d_in[5];
    const float* bv  = (const float*)d_in[6];
    float* out = (float*)d_out;

    cudaFuncSetAttribute(qkv_gemm,
                         cudaFuncAttributeMaxDynamicSharedMemorySize, SMEM_G);

    round_val<<<(size_t)NROWS * DMODEL / 1024, 256>>>(val);
    round_w<<<dim3(DMODEL * DMODEL / 1024, 3), 256>>>(Wq, Wk, Wv);

    dim3 g1(DMODEL / GN, NROWS / GM, 3);    // 6 x 32 x 3
    qkv_gemm<<<g1, 256, SMEM_G>>>(bq, bk, bv);

    dim3 g2(S_LEN / QBLK2, NHEAD, BATCH);   // 32 x 12 x 2
    attn_kernel<<<g2, 128>>>(out);
}

// round 7
// speedup vs baseline: 1.8795x; 1.8795x over previous
#include <cuda_runtime.h>
#include <cstdint>

#define S_LEN  4096
#define BATCH  2
#define DMODEL 768
#define NHEAD  12
#define HDIM   64
#define WSZ    256
#define NROWS  (S_LEN * BATCH)   // 8192

// scratch (device globals: allowed, no allocation)
__device__ float g_q [(size_t)NROWS * DMODEL];
__device__ float g_k [(size_t)NROWS * DMODEL];
__device__ float g_v [(size_t)NROWS * DMODEL];
__device__ float g_ar[(size_t)NROWS * DMODEL];        // tf32-rounded activations
__device__ float g_w3[(size_t)3 * DMODEL * DMODEL];   // tf32-rounded W (row-major)

// ---------------------------------------------------------------------------
// helpers
// ---------------------------------------------------------------------------
__device__ __forceinline__ unsigned long long pk2(float x, float y) {
    unsigned long long r;
    asm("mov.b64 %0,{%1,%2};" : "=l"(r) : "f"(x), "f"(y));
    return r;
}
__device__ __forceinline__ void upk2(unsigned long long v, float& x, float& y) {
    asm("mov.b64 {%0,%1},%2;" : "=f"(x), "=f"(y) : "l"(v));
}
__device__ __forceinline__ unsigned long long fma2_(unsigned long long a,
                                                    unsigned long long b,
                                                    unsigned long long c) {
    unsigned long long d;
    asm("fma.rn.f32x2 %0,%1,%2,%3;" : "=l"(d) : "l"(a), "l"(b), "l"(c));
    return d;
}
__device__ __forceinline__ unsigned long long mul2_(unsigned long long a,
                                                    unsigned long long b) {
    unsigned long long d;
    asm("mul.rn.f32x2 %0,%1,%2;" : "=l"(d) : "l"(a), "l"(b));
    return d;
}
__device__ __forceinline__ float tf32f(float x) {
    uint32_t u;
    asm("cvt.rna.tf32.f32 %0,%1;" : "=r"(u) : "f"(x));
    return __uint_as_float(u);
}
__device__ __forceinline__ uint32_t s2u(const void* p) {
    uint32_t a;
    asm("{ .reg .u64 t; cvta.to.shared.u64 t, %1; cvt.u32.u64 %0, t; }"
        : "=r"(a) : "l"(p));
    return a;
}
__device__ __forceinline__ void cpa16(uint32_t dst, const void* src) {
    asm volatile("cp.async.cg.shared.global [%0], [%1], 16;"
                 :: "r"(dst), "l"(src));
}
__device__ __forceinline__ void mma_tf32(float c[4], const uint32_t a[4],
                                         const uint32_t b[2]) {
    asm volatile(
        "mma.sync.aligned.m16n8k8.row.col.f32.tf32.tf32.f32 "
        "{%0,%1,%2,%3},{%4,%5,%6,%7},{%8,%9},{%0,%1,%2,%3};"
        : "+f"(c[0]), "+f"(c[1]), "+f"(c[2]), "+f"(c[3])
        : "r"(a[0]), "r"(a[1]), "r"(a[2]), "r"(a[3]), "r"(b[0]), "r"(b[1]));
}

// ---------------------------------------------------------------------------
// prepasses: tf32 rounding (RNA) of activations and weights
// ---------------------------------------------------------------------------
__global__ __launch_bounds__(256) void round_val(const float* __restrict__ val)
{
    size_t i = ((size_t)blockIdx.x * 256 + threadIdx.x) * 4;
    float4 v = *(const float4*)(val + i);
    v.x = tf32f(v.x); v.y = tf32f(v.y); v.z = tf32f(v.z); v.w = tf32f(v.w);
    *(float4*)(g_ar + i) = v;
}

__global__ __launch_bounds__(256) void round_w(
    const float* __restrict__ Wq, const float* __restrict__ Wk,
    const float* __restrict__ Wv)
{
    const int z = blockIdx.y;
    const float* W = (z == 0) ? Wq : (z == 1) ? Wk : Wv;
    size_t i = ((size_t)blockIdx.x * 256 + threadIdx.x) * 4;
    float4 v = *(const float4*)(W + i);
    v.x = tf32f(v.x); v.y = tf32f(v.y); v.z = tf32f(v.z); v.w = tf32f(v.w);
    *(float4*)(g_w3 + (size_t)z * DMODEL * DMODEL + i) = v;
}

// ---------------------------------------------------------------------------
// Kernel 1: QKV projection, legacy mma.sync tf32, cp.async 3-stage pipeline.
// (verbatim from R5 run: ~183 us, near legacy-tensor ceiling)
// ---------------------------------------------------------------------------
#define GM 256
#define GN 128
#define KC 32
#define NST (DMODEL / KC)             // 24
#define ASTR 36
#define BSTR 136
#define AWORDS (GM * ASTR)            // 9216
#define STWORDS (AWORDS + KC * BSTR)  // 13568
#define SMEM_G (3 * STWORDS * 4)      // 162816 bytes

__global__ __launch_bounds__(256, 1) void qkv_gemm(
    const float* __restrict__ bq, const float* __restrict__ bk,
    const float* __restrict__ bv)
{
    extern __shared__ __align__(16) float smem[];
    const uint32_t sb = s2u(smem);

    const int tid  = threadIdx.x;
    const int lane = tid & 31;
    const int w    = tid >> 5;
    const int wm   = (w & 3) * 64;
    const int wn   = (w >> 2) * 64;
    const int qd   = lane >> 2;      // 0..7
    const int kl   = lane & 3;       // 0..3

    const int z = blockIdx.z;
    const float* __restrict__ Wt   = g_w3 + (size_t)z * DMODEL * DMODEL;
    const float* __restrict__ bias = (z == 0) ? bq : (z == 1) ? bk : bv;
    float* outp = (z == 0) ? g_q : (z == 1) ? g_k : g_v;
    const float scale = (z == 0) ? 0.125f : 1.0f;
    const int bm = blockIdx.y * GM;
    const int bn = blockIdx.x * GN;

    float acc[4][8][4];
#pragma unroll
    for (int mt = 0; mt < 4; mt++)
#pragma unroll
        for (int nt = 0; nt < 8; nt++)
#pragma unroll
            for (int i = 0; i < 4; i++) acc[mt][nt][i] = 0.f;

    auto load_stage = [&](int s) {
        const uint32_t base = sb + (uint32_t)(s % 3) * (STWORDS * 4);
        const int k0 = s * KC;
#pragma unroll
        for (int i = 0; i < 8; i++) {
            const int c  = tid + 256 * i;
            const int m  = c >> 3;
            const int k4 = (c & 7) * 4;
            cpa16(base + (uint32_t)(m * ASTR + k4) * 4,
                  g_ar + (size_t)(bm + m) * DMODEL + k0 + k4);
        }
#pragma unroll
        for (int i = 0; i < 4; i++) {
            const int c  = tid + 256 * i;
            const int kr = c >> 5;
            const int n4 = (c & 31) * 4;
            cpa16(base + (uint32_t)(AWORDS + kr * BSTR + n4) * 4,
                  Wt + (size_t)(k0 + kr) * DMODEL + bn + n4);
        }
        asm volatile("cp.async.commit_group;" ::: "memory");
    };

    load_stage(0); load_stage(1); load_stage(2);

    for (int s = 0; s < NST; s++) {
        asm volatile("cp.async.wait_group 2;" ::: "memory");
        __syncthreads();

        const float* As = smem + (s % 3) * STWORDS;
        const float* Bs = As + AWORDS;

#pragma unroll
        for (int ks = 0; ks < 4; ks++) {
            const int kc = ks * 8 + kl;
            uint32_t af[4][4];
#pragma unroll
            for (int mt = 0; mt < 4; mt++) {
                const int r = wm + mt * 16 + qd;
                af[mt][0] = __float_as_uint(As[r * ASTR + kc]);
                af[mt][1] = __float_as_uint(As[(r + 8) * ASTR + kc]);
                af[mt][2] = __float_as_uint(As[r * ASTR + kc + 4]);
                af[mt][3] = __float_as_uint(As[(r + 8) * ASTR + kc + 4]);
            }
            uint32_t bf[8][2];
#pragma unroll
            for (int nt = 0; nt < 8; nt++) {
                const int cc = wn + nt * 8 + qd;
                bf[nt][0] = __float_as_uint(Bs[kc * BSTR + cc]);
                bf[nt][1] = __float_as_uint(Bs[(kc + 4) * BSTR + cc]);
            }
#pragma unroll
            for (int mt = 0; mt < 4; mt++)
#pragma unroll
                for (int nt = 0; nt < 8; nt++)
                    mma_tf32(acc[mt][nt], af[mt], bf[nt]);
        }

        __syncthreads();
        if (s + 3 < NST) load_stage(s + 3);
        else asm volatile("cp.async.commit_group;" ::: "memory");  // keep count
    }

#pragma unroll
    for (int mt = 0; mt < 4; mt++) {
        const int row0 = bm + wm + mt * 16 + qd;
#pragma unroll
        for (int nt = 0; nt < 8; nt++) {
            const int col = bn + wn + nt * 8 + 2 * kl;
            const float2 b2 = *(const float2*)(bias + col);
            float2 o0, o1;
            o0.x = (acc[mt][nt][0] + b2.x) * scale;
            o0.y = (acc[mt][nt][1] + b2.y) * scale;
            o1.x = (acc[mt][nt][2] + b2.x) * scale;
            o1.y = (acc[mt][nt][3] + b2.y) * scale;
            *(float2*)(outp + (size_t)row0 * DMODEL + col)       = o0;
            *(float2*)(outp + (size_t)(row0 + 8) * DMODEL + col) = o1;
        }
    }
}

// ---------------------------------------------------------------------------
// Kernel 2: causal sliding-window attention (verbatim from R2 run: 323 us).
// 2 lanes per query: lane owns 32 of 64 dims; partner via shfl.xor(1).
// Packed f32x2 FMA.  Block = 64 queries of one (b,h).
// K/V tiles in smem with +4-float offset for the upper half (bank-disjoint).
// ---------------------------------------------------------------------------
#define QBLK  64
#define KTILE 64
#define ROWST 72    // smem row stride in floats

__global__ __launch_bounds__(128) void attn_kernel(float* __restrict__ out)
{
    __shared__ float Ks[KTILE][ROWST];
    __shared__ float Vs[KTILE][ROWST];

    const int tid   = threadIdx.x;
    const int h     = blockIdx.y;
    const int b     = blockIdx.z;
    const int q0    = blockIdx.x * QBLK;
    const int qi    = q0 + (tid >> 1);          // absolute query index
    const int half  = tid & 1;                  // which 32-dim half
    const int wq    = q0 + (tid >> 5) * 16;     // warp-uniform query base (16 q/warp)

    // load this thread's half of q (already scaled by 1/sqrt(hd))
    unsigned long long q2[16];
    {
        const ulonglong2* qg = (const ulonglong2*)(
            g_q + ((size_t)qi * BATCH + b) * DMODEL + h * HDIM + half * 32);
#pragma unroll
        for (int i = 0; i < 8; i++) {
            ulonglong2 t = qg[i];
            q2[2 * i]     = t.x;
            q2[2 * i + 1] = t.y;
        }
    }

    unsigned long long acc2[16];
#pragma unroll
    for (int i = 0; i < 16; i++) acc2[i] = 0ull;
    float m = -1e30f, l = 0.f;

    const int jstart = q0 - WSZ;   // span QBLK + WSZ = 320 keys = 5 tiles

    for (int t = 0; t < 5; t++) {
        const int j0 = jstart + t * KTILE;
        if (j0 + KTILE <= 0) continue;          // tile fully before sequence
        __syncthreads();
        // cooperative fill (zero out-of-range), upper half shifted +4 floats
#pragma unroll
        for (int it = 0; it < 8; it++) {
            const int f   = tid + 128 * it;
            const int row = f >> 4;
            const int c4  = (f & 15) << 2;
            const int col = c4 + (c4 >= 32 ? 4 : 0);
            const int j   = j0 + row;
            float4 kk4 = make_float4(0.f, 0.f, 0.f, 0.f);
            float4 vv4 = make_float4(0.f, 0.f, 0.f, 0.f);
            if (j >= 0 && j < S_LEN) {
                const size_t base = ((size_t)j * BATCH + b) * DMODEL + h * HDIM + c4;
                kk4 = *(const float4*)(g_k + base);
                vv4 = *(const float4*)(g_v + base);
            }
            *(float4*)&Ks[row][col] = kk4;
            *(float4*)&Vs[row][col] = vv4;
        }
        __syncthreads();

        for (int jj = 0; jj < KTILE; jj++) {
            const int j = j0 + jj;
            // warp-uniform key liveness
            if (j < 0)          continue;
            if (j > wq + 15)    continue;
            if (j < wq - WSZ)   continue;

            // partial dot over own 32 dims (packed)
            unsigned long long s2 = 0ull;
            const ulonglong2* kr = (const ulonglong2*)&Ks[jj][half * 36];
#pragma unroll
            for (int i = 0; i < 8; i++) {
                ulonglong2 kk = kr[i];
                s2 = fma2_(q2[2 * i], kk.x, s2);
                s2 = fma2_(q2[2 * i + 1], kk.y, s2);
            }
            float sx, sy;
            upk2(s2, sx, sy);
            float s = sx + sy;
            s += __shfl_xor_sync(0xffffffffu, s, 1);

            if (j <= qi && j >= qi - WSZ) {
                if (s > m) {                        // lazy rescale (exact)
                    const float sc = __expf(m - s);
                    m = s;
                    l *= sc;
                    const unsigned long long sc2 = pk2(sc, sc);
#pragma unroll
                    for (int i = 0; i < 16; i++) acc2[i] = mul2_(acc2[i], sc2);
                }
                const float p = __expf(s - m);
                l += p;
                const unsigned long long p2 = pk2(p, p);
                const ulonglong2* vr = (const ulonglong2*)&Vs[jj][half * 36];
#pragma unroll
                for (int i = 0; i < 8; i++) {
                    ulonglong2 vv = vr[i];
                    acc2[2 * i]     = fma2_(p2, vv.x, acc2[2 * i]);
                    acc2[2 * i + 1] = fma2_(p2, vv.y, acc2[2 * i + 1]);
                }
            }
        }
    }

    const float inv = 1.f / l;
    float* og = out + ((size_t)qi * BATCH + b) * DMODEL + h * HDIM + half * 32;
#pragma unroll
    for (int i = 0; i < 8; i++) {
        float x0, y0, x1, y1;
        upk2(acc2[2 * i], x0, y0);
        upk2(acc2[2 * i + 1], x1, y1);
        *(float4*)(og + 4 * i) =
            make_float4(x0 * inv, y0 * inv, x1 * inv, y1 * inv);
    }
}

// ---------------------------------------------------------------------------
extern "C" void kernel_launch(void* const* d_in, const int* in_sizes, int n_in,
                              void* d_out, int out_size)
{
    const float* val = (const float*)d_in[0];
    const float* Wq  = (const float*)d_in[1];
    const float* bq  = (const float*)d_in[2];
    const float* Wk  = (const float*)d_in[3];
    const float* bk  = (const float*)d_in[4];
    const float* Wv  = (const float*)d_in[5];
    const float* bv  = (const float*)d_in[6];
    float* out = (float*)d_out;

    cudaFuncSetAttribute(qkv_gemm,
                         cudaFuncAttributeMaxDynamicSharedMemorySize, SMEM_G);

    round_val<<<(size_t)NROWS * DMODEL / 1024, 256>>>(val);
    round_w<<<dim3(DMODEL * DMODEL / 1024, 3), 256>>>(Wq, Wk, Wv);

    dim3 g1(DMODEL / GN, NROWS / GM, 3);    // 6 x 32 x 3
    qkv_gemm<<<g1, 256, SMEM_G>>>(bq, bk, bv);

    dim3 g2(S_LEN / QBLK, NHEAD, BATCH);    // 64 x 12 x 2
    attn_kernel<<<g2, 128>>>(out);
}

// round 10
// speedup vs baseline: 3.3629x; 1.7893x over previous
#include <cuda_runtime.h>
#include <cstdint>

#define S_LEN  4096
#define BATCH  2
#define DMODEL 768
#define NHEAD  12
#define HDIM   64
#define WSZ    256
#define NROWS  (S_LEN * BATCH)   // 8192

// scratch (device globals: allowed, no allocation)
__device__ float g_q [(size_t)NROWS * DMODEL];
__device__ float g_k [(size_t)NROWS * DMODEL];
__device__ float g_v [(size_t)NROWS * DMODEL];
__device__ float g_ar[(size_t)NROWS * DMODEL];        // tf32-rounded activations
__device__ float g_w3[(size_t)3 * DMODEL * DMODEL];   // tf32-rounded W (row-major)

// ---------------------------------------------------------------------------
// helpers
// ---------------------------------------------------------------------------
__device__ __forceinline__ float tf32f(float x) {
    uint32_t u;
    asm("cvt.rna.tf32.f32 %0,%1;" : "=r"(u) : "f"(x));
    return __uint_as_float(u);
}
__device__ __forceinline__ uint32_t s2u(const void* p) {
    uint32_t a;
    asm("{ .reg .u64 t; cvta.to.shared.u64 t, %1; cvt.u32.u64 %0, t; }"
        : "=r"(a) : "l"(p));
    return a;
}
__device__ __forceinline__ void cpa16(uint32_t dst, const void* src) {
    asm volatile("cp.async.cg.shared.global [%0], [%1], 16;"
                 :: "r"(dst), "l"(src));
}
__device__ __forceinline__ void mma_tf32(float c[4], const uint32_t a[4],
                                         const uint32_t b[2]) {
    asm volatile(
        "mma.sync.aligned.m16n8k8.row.col.f32.tf32.tf32.f32 "
        "{%0,%1,%2,%3},{%4,%5,%6,%7},{%8,%9},{%0,%1,%2,%3};"
        : "+f"(c[0]), "+f"(c[1]), "+f"(c[2]), "+f"(c[3])
        : "r"(a[0]), "r"(a[1]), "r"(a[2]), "r"(a[3]), "r"(b[0]), "r"(b[1]));
}

// ---------------------------------------------------------------------------
// prepasses: tf32 rounding (RNA) of activations and weights
// ---------------------------------------------------------------------------
__global__ __launch_bounds__(256) void round_val(const float* __restrict__ val)
{
    size_t i = ((size_t)blockIdx.x * 256 + threadIdx.x) * 4;
    float4 v = *(const float4*)(val + i);
    v.x = tf32f(v.x); v.y = tf32f(v.y); v.z = tf32f(v.z); v.w = tf32f(v.w);
    *(float4*)(g_ar + i) = v;
}

__global__ __launch_bounds__(256) void round_w(
    const float* __restrict__ Wq, const float* __restrict__ Wk,
    const float* __restrict__ Wv)
{
    const int z = blockIdx.y;
    const float* W = (z == 0) ? Wq : (z == 1) ? Wk : Wv;
    size_t i = ((size_t)blockIdx.x * 256 + threadIdx.x) * 4;
    float4 v = *(const float4*)(W + i);
    v.x = tf32f(v.x); v.y = tf32f(v.y); v.z = tf32f(v.z); v.w = tf32f(v.w);
    *(float4*)(g_w3 + (size_t)z * DMODEL * DMODEL + i) = v;
}

// ---------------------------------------------------------------------------
// Kernel 1: QKV projection, legacy mma.sync tf32, cp.async 3-stage pipeline.
// (as R5/R7 run: ~183 us; epilogue RNA-rounds outputs to tf32 so the
//  attention mma consumes exactly-tf32 values)
// ---------------------------------------------------------------------------
#define GM 256
#define GN 128
#define KC 32
#define NST (DMODEL / KC)             // 24
#define ASTR 36
#define BSTR 136
#define AWORDS (GM * ASTR)            // 9216
#define STWORDS (AWORDS + KC * BSTR)  // 13568
#define SMEM_G (3 * STWORDS * 4)      // 162816 bytes

__global__ __launch_bounds__(256, 1) void qkv_gemm(
    const float* __restrict__ bq, const float* __restrict__ bk,
    const float* __restrict__ bv)
{
    extern __shared__ __align__(16) float smem[];
    const uint32_t sb = s2u(smem);

    const int tid  = threadIdx.x;
    const int lane = tid & 31;
    const int w    = tid >> 5;
    const int wm   = (w & 3) * 64;
    const int wn   = (w >> 2) * 64;
    const int qd   = lane >> 2;      // 0..7
    const int kl   = lane & 3;       // 0..3

    const int z = blockIdx.z;
    const float* __restrict__ Wt   = g_w3 + (size_t)z * DMODEL * DMODEL;
    const float* __restrict__ bias = (z == 0) ? bq : (z == 1) ? bk : bv;
    float* outp = (z == 0) ? g_q : (z == 1) ? g_k : g_v;
    const float scale = (z == 0) ? 0.125f : 1.0f;
    const int bm = blockIdx.y * GM;
    const int bn = blockIdx.x * GN;

    float acc[4][8][4];
#pragma unroll
    for (int mt = 0; mt < 4; mt++)
#pragma unroll
        for (int nt = 0; nt < 8; nt++)
#pragma unroll
            for (int i = 0; i < 4; i++) acc[mt][nt][i] = 0.f;

    auto load_stage = [&](int s) {
        const uint32_t base = sb + (uint32_t)(s % 3) * (STWORDS * 4);
        const int k0 = s * KC;
#pragma unroll
        for (int i = 0; i < 8; i++) {
            const int c  = tid + 256 * i;
            const int m  = c >> 3;
            const int k4 = (c & 7) * 4;
            cpa16(base + (uint32_t)(m * ASTR + k4) * 4,
                  g_ar + (size_t)(bm + m) * DMODEL + k0 + k4);
        }
#pragma unroll
        for (int i = 0; i < 4; i++) {
            const int c  = tid + 256 * i;
            const int kr = c >> 5;
            const int n4 = (c & 31) * 4;
            cpa16(base + (uint32_t)(AWORDS + kr * BSTR + n4) * 4,
                  Wt + (size_t)(k0 + kr) * DMODEL + bn + n4);
        }
        asm volatile("cp.async.commit_group;" ::: "memory");
    };

    load_stage(0); load_stage(1); load_stage(2);

    for (int s = 0; s < NST; s++) {
        asm volatile("cp.async.wait_group 2;" ::: "memory");
        __syncthreads();

        const float* As = smem + (s % 3) * STWORDS;
        const float* Bs = As + AWORDS;

#pragma unroll
        for (int ks = 0; ks < 4; ks++) {
            const int kc = ks * 8 + kl;
            uint32_t af[4][4];
#pragma unroll
            for (int mt = 0; mt < 4; mt++) {
                const int r = wm + mt * 16 + qd;
                af[mt][0] = __float_as_uint(As[r * ASTR + kc]);
                af[mt][1] = __float_as_uint(As[(r + 8) * ASTR + kc]);
                af[mt][2] = __float_as_uint(As[r * ASTR + kc + 4]);
                af[mt][3] = __float_as_uint(As[(r + 8) * ASTR + kc + 4]);
            }
            uint32_t bf[8][2];
#pragma unroll
            for (int nt = 0; nt < 8; nt++) {
                const int cc = wn + nt * 8 + qd;
                bf[nt][0] = __float_as_uint(Bs[kc * BSTR + cc]);
                bf[nt][1] = __float_as_uint(Bs[(kc + 4) * BSTR + cc]);
            }
#pragma unroll
            for (int mt = 0; mt < 4; mt++)
#pragma unroll
                for (int nt = 0; nt < 8; nt++)
                    mma_tf32(acc[mt][nt], af[mt], bf[nt]);
        }

        __syncthreads();
        if (s + 3 < NST) load_stage(s + 3);
        else asm volatile("cp.async.commit_group;" ::: "memory");  // keep count
    }

    // epilogue: bias + scale, RNA-round to tf32, 8B stores
#pragma unroll
    for (int mt = 0; mt < 4; mt++) {
        const int row0 = bm + wm + mt * 16 + qd;
#pragma unroll
        for (int nt = 0; nt < 8; nt++) {
            const int col = bn + wn + nt * 8 + 2 * kl;
            const float2 b2 = *(const float2*)(bias + col);
            float2 o0, o1;
            o0.x = tf32f((acc[mt][nt][0] + b2.x) * scale);
            o0.y = tf32f((acc[mt][nt][1] + b2.y) * scale);
            o1.x = tf32f((acc[mt][nt][2] + b2.x) * scale);
            o1.y = tf32f((acc[mt][nt][3] + b2.y) * scale);
            *(float2*)(outp + (size_t)row0 * DMODEL + col)       = o0;
            *(float2*)(outp + (size_t)(row0 + 8) * DMODEL + col) = o1;
        }
    }
}

// ---------------------------------------------------------------------------
// Kernel 2: flash-style causal sliding-window attention on tensor cores.
// Block = 64 queries of one (b,h), 4 warps x 16 queries.
// Per 64-key chunk: S = Q K^T (mma), chunk-level online softmax,
// P -> per-warp smem, O += P V (mma).  cp.async double-buffered K/V.
// Smem strides: K 68 (B-frag banks 4r+c), V 72 (8c+r), P 68 (4r+c) — clean.
// ---------------------------------------------------------------------------
#define KWORDS 4352            // 64*68
#define VWORDS 4608            // 64*72
#define PWORDS 1088            // 16*68
#define SMEM_A ((2*KWORDS + 2*VWORDS + 4*PWORDS) * 4)   // 89088 bytes

__global__ __launch_bounds__(128) void attn_mma(float* __restrict__ out)
{
    extern __shared__ __align__(16) float sm[];
    const uint32_t smb = s2u(sm);

    const int tid  = threadIdx.x;
    const int lane = tid & 31;
    const int wid  = tid >> 5;
    const int h    = blockIdx.y;
    const int b    = blockIdx.z;
    const int q0   = blockIdx.x * 64;
    const int r    = lane >> 2;     // mma group id
    const int c    = lane & 3;      // mma thread-in-group
    const int qa   = q0 + wid * 16 + r;          // absolute query (and +8)

    float* Pw = sm + 2 * KWORDS + 2 * VWORDS + wid * PWORDS;

    // Q fragments (values already tf32-rounded by the GEMM epilogue)
    uint32_t aq[8][4];
    {
        const float* q_lo = g_q + ((size_t)qa * BATCH + b) * DMODEL + h * HDIM;
        const float* q_hi = q_lo + (size_t)8 * BATCH * DMODEL;
#pragma unroll
        for (int kt = 0; kt < 8; kt++) {
            aq[kt][0] = __float_as_uint(q_lo[kt * 8 + c]);
            aq[kt][1] = __float_as_uint(q_hi[kt * 8 + c]);
            aq[kt][2] = __float_as_uint(q_lo[kt * 8 + c + 4]);
            aq[kt][3] = __float_as_uint(q_hi[kt * 8 + c + 4]);
        }
    }

    float oacc[8][4];
#pragma unroll
    for (int nt = 0; nt < 8; nt++)
#pragma unroll
        for (int i = 0; i < 4; i++) oacc[nt][i] = 0.f;
    float m0 = -1e30f, m1 = -1e30f, l0 = 0.f, l1 = 0.f;

    const int t_start = (q0 >= WSZ) ? 0 : ((WSZ - q0) >> 6);
    const int nch     = 5 - t_start;
    const int kbase0  = q0 - WSZ + t_start * 64;   // >= 0, 64-aligned

    auto load_chunk = [&](int u) {
        const int cb = kbase0 + u * 64;
        const uint32_t kd = smb + (uint32_t)((u & 1) * KWORDS) * 4;
        const uint32_t vd = smb + (uint32_t)(2 * KWORDS + (u & 1) * VWORDS) * 4;
        const size_t gb = ((size_t)cb * BATCH + b) * DMODEL + h * HDIM;
#pragma unroll
        for (int it = 0; it < 8; it++) {
            const int f   = tid + 128 * it;
            const int row = f >> 4;
            const int ch  = (f & 15) * 4;
            const size_t g = gb + (size_t)row * (BATCH * DMODEL) + ch;
            cpa16(kd + (uint32_t)(row * 68 + ch) * 4, g_k + g);
            cpa16(vd + (uint32_t)(row * 72 + ch) * 4, g_v + g);
        }
        asm volatile("cp.async.commit_group;" ::: "memory");
    };

    load_chunk(0);
    if (nch > 1) load_chunk(1);
    else asm volatile("cp.async.commit_group;" ::: "memory");

    const float NEGINF = __int_as_float(0xff800000);

    for (int u = 0; u < nch; u++) {
        asm volatile("cp.async.wait_group 1;" ::: "memory");
        __syncthreads();

        const float* Kb = sm + (u & 1) * KWORDS;
        const float* Vb = sm + 2 * KWORDS + (u & 1) * VWORDS;
        const int cb = kbase0 + u * 64;

        // ---- S = Q K^T ----
        float sacc[8][4];
#pragma unroll
        for (int nt = 0; nt < 8; nt++)
#pragma unroll
            for (int i = 0; i < 4; i++) sacc[nt][i] = 0.f;
#pragma unroll
        for (int kt = 0; kt < 8; kt++) {
#pragma unroll
            for (int nt = 0; nt < 8; nt++) {
                uint32_t bf[2];
                const float* kp = Kb + (8 * nt + r) * 68 + 8 * kt + c;
                bf[0] = __float_as_uint(kp[0]);
                bf[1] = __float_as_uint(kp[4]);
                mma_tf32(sacc[nt], aq[kt], bf);
            }
        }

        // ---- mask + rowmax ----
        float rmax0 = NEGINF, rmax1 = NEGINF;
#pragma unroll
        for (int nt = 0; nt < 8; nt++) {
            const int j = cb + 8 * nt + 2 * c;
            sacc[nt][0] = ((unsigned)(qa - j)         <= WSZ) ? sacc[nt][0] : NEGINF;
            sacc[nt][1] = ((unsigned)(qa - j - 1)     <= WSZ) ? sacc[nt][1] : NEGINF;
            sacc[nt][2] = ((unsigned)(qa + 8 - j)     <= WSZ) ? sacc[nt][2] : NEGINF;
            sacc[nt][3] = ((unsigned)(qa + 8 - j - 1) <= WSZ) ? sacc[nt][3] : NEGINF;
            rmax0 = fmaxf(rmax0, fmaxf(sacc[nt][0], sacc[nt][1]));
            rmax1 = fmaxf(rmax1, fmaxf(sacc[nt][2], sacc[nt][3]));
        }
        rmax0 = fmaxf(rmax0, __shfl_xor_sync(0xffffffffu, rmax0, 1));
        rmax0 = fmaxf(rmax0, __shfl_xor_sync(0xffffffffu, rmax0, 2));
        rmax1 = fmaxf(rmax1, __shfl_xor_sync(0xffffffffu, rmax1, 1));
        rmax1 = fmaxf(rmax1, __shfl_xor_sync(0xffffffffu, rmax1, 2));

        const float mn0 = fmaxf(m0, rmax0), mn1 = fmaxf(m1, rmax1);
        const float f0 = __expf(m0 - mn0), f1 = __expf(m1 - mn1);
        m0 = mn0; m1 = mn1;

        // ---- exp, rowsum, P -> smem (RNA-rounded) ----
        __syncwarp();
        float rs0 = 0.f, rs1 = 0.f;
#pragma unroll
        for (int nt = 0; nt < 8; nt++) {
            const float p00 = __expf(sacc[nt][0] - m0);
            const float p01 = __expf(sacc[nt][1] - m0);
            const float p10 = __expf(sacc[nt][2] - m1);
            const float p11 = __expf(sacc[nt][3] - m1);
            rs0 += p00 + p01;
            rs1 += p10 + p11;
            *(float2*)&Pw[r * 68 + 8 * nt + 2 * c] =
                make_float2(tf32f(p00), tf32f(p01));
            *(float2*)&Pw[(r + 8) * 68 + 8 * nt + 2 * c] =
                make_float2(tf32f(p10), tf32f(p11));
        }
        rs0 += __shfl_xor_sync(0xffffffffu, rs0, 1);
        rs0 += __shfl_xor_sync(0xffffffffu, rs0, 2);
        rs1 += __shfl_xor_sync(0xffffffffu, rs1, 1);
        rs1 += __shfl_xor_sync(0xffffffffu, rs1, 2);
        l0 = l0 * f0 + rs0;
        l1 = l1 * f1 + rs1;
#pragma unroll
        for (int nt = 0; nt < 8; nt++) {
            oacc[nt][0] *= f0; oacc[nt][1] *= f0;
            oacc[nt][2] *= f1; oacc[nt][3] *= f1;
        }
        __syncwarp();

        // ---- O += P V ----
#pragma unroll
        for (int kt = 0; kt < 8; kt++) {
            uint32_t ap[4];
            ap[0] = __float_as_uint(Pw[r * 68 + 8 * kt + c]);
            ap[1] = __float_as_uint(Pw[(r + 8) * 68 + 8 * kt + c]);
            ap[2] = __float_as_uint(Pw[r * 68 + 8 * kt + c + 4]);
            ap[3] = __float_as_uint(Pw[(r + 8) * 68 + 8 * kt + c + 4]);
#pragma unroll
            for (int nt = 0; nt < 8; nt++) {
                uint32_t bf[2];
                const float* vp = Vb + (8 * kt + c) * 72 + 8 * nt + r;
                bf[0] = __float_as_uint(vp[0]);
                bf[1] = __float_as_uint(vp[4 * 72]);
                mma_tf32(oacc[nt], ap, bf);
            }
        }

        __syncthreads();
        if (u + 2 < nch) load_chunk(u + 2);
        else asm volatile("cp.async.commit_group;" ::: "memory");
    }

    // ---- epilogue ----
    const float i0 = 1.f / l0, i1 = 1.f / l1;
    float* o_lo = out + ((size_t)qa * BATCH + b) * DMODEL + h * HDIM;
    float* o_hi = o_lo + (size_t)8 * BATCH * DMODEL;
#pragma unroll
    for (int nt = 0; nt < 8; nt++) {
        *(float2*)&o_lo[8 * nt + 2 * c] =
            make_float2(oacc[nt][0] * i0, oacc[nt][1] * i0);
        *(float2*)&o_hi[8 * nt + 2 * c] =
            make_float2(oacc[nt][2] * i1, oacc[nt][3] * i1);
    }
}

// ---------------------------------------------------------------------------
extern "C" void kernel_launch(void* const* d_in, const int* in_sizes, int n_in,
                              void* d_out, int out_size)
{
    const float* val = (const float*)d_in[0];
    const float* Wq  = (const float*)d_in[1];
    const float* bq  = (const float*)d_in[2];
    const float* Wk  = (const float*)d_in[3];
    const float* bk  = (const float*)d_in[4];
    const float* Wv  = (const float*)d_in[5];
    const float* bv  = (const float*)d_in[6];
    float* out = (float*)d_out;

    cudaFuncSetAttribute(qkv_gemm,
                         cudaFuncAttributeMaxDynamicSharedMemorySize, SMEM_G);
    cudaFuncSetAttribute(attn_mma,
                         cudaFuncAttributeMaxDynamicSharedMemorySize, SMEM_A);

    round_val<<<(size_t)NROWS * DMODEL / 1024, 256>>>(val);
    round_w<<<dim3(DMODEL * DMODEL / 1024, 3), 256>>>(Wq, Wk, Wv);

    dim3 g1(DMODEL / GN, NROWS / GM, 3);    // 6 x 32 x 3
    qkv_gemm<<<g1, 256, SMEM_G>>>(bq, bk, bv);

    dim3 g2(S_LEN / 64, NHEAD, BATCH);      // 64 x 12 x 2
    attn_mma<<<g2, 128, SMEM_A>>>(out);
}